// round 10
// baseline (speedup 1.0000x reference)
#include <cuda_runtime.h>
#include <cuda_bf16.h>
#include <cstdint>

#define T_SEQ 1024
#define B_SZ  256

// ---------------- device scratch (allocation-free statics) ----------------
__device__ float g_XW[262144ull * 1024];            // xw fp32 [t*B+b][<=1024]
__device__ __nv_bfloat16 g_Ap[262144ull * 768];     // split-bf16 A' [row][3K]
__device__ __nv_bfloat16 g_Wp[1024ull * 768];       // split-bf16 W' [row][3K]
__device__ float g_XWB3[256 * 256];
__device__ float g_H3[256 * 128];
__device__ float g_F1[256 * 512];
__device__ float g_F2[256 * 256];
__device__ float g_F3[256 * 128];

// ---------------- portable PTX helpers ----------------
__device__ __forceinline__ uint32_t smem_to_u32(const void* p) {
    uint32_t a;
    asm("{ .reg .u64 t; cvta.to.shared.u64 t, %1; cvt.u32.u64 %0, t; }" : "=r"(a) : "l"(p));
    return a;
}
__device__ __forceinline__ void cp_async16(uint32_t dst, const void* src) {
    asm volatile("cp.async.cg.shared.global [%0], [%1], 16;" :: "r"(dst), "l"(src) : "memory");
}
__device__ __forceinline__ void cp_commit() {
    asm volatile("cp.async.commit_group;" ::: "memory");
}
template<int N>
__device__ __forceinline__ void cp_wait() {
    asm volatile("cp.async.wait_group %0;" :: "n"(N) : "memory");
}
#define LDSM_X4(r, addr) \
    asm volatile("ldmatrix.sync.aligned.m8n8.x4.shared.b16 {%0,%1,%2,%3}, [%4];" \
        : "=r"((r)[0]), "=r"((r)[1]), "=r"((r)[2]), "=r"((r)[3]) : "r"(addr))
#define MMA16816(d, a, b0, b1) \
    asm volatile("mma.sync.aligned.m16n8k16.row.col.f32.bf16.bf16.f32 " \
        "{%0,%1,%2,%3}, {%4,%5,%6,%7}, {%8,%9}, {%0,%1,%2,%3};" \
        : "+f"((d)[0]), "+f"((d)[1]), "+f"((d)[2]), "+f"((d)[3]) \
        : "r"((a)[0]), "r"((a)[1]), "r"((a)[2]), "r"((a)[3]), "r"(b0), "r"(b1))

// packed fp32x2 FMA (Blackwell dual-lane fp32): d = a*b + d, lanewise
__device__ __forceinline__ void fma2(uint64_t& d, uint64_t a, uint64_t b) {
    asm("fma.rn.f32x2 %0, %1, %2, %0;" : "+l"(d) : "l"(a), "l"(b));
}
__device__ __forceinline__ uint64_t pack2(float a, float b) {
    uint64_t r;
    asm("mov.b64 %0, {%1, %2};" : "=l"(r) : "f"(a), "f"(b));
    return r;
}
__device__ __forceinline__ void unpack2(uint64_t v, float& a, float& b) {
    asm("mov.b64 {%0, %1}, %2;" : "=f"(a), "=f"(b) : "l"(v));
}
__device__ __forceinline__ float hadd2(uint64_t v) {
    float a, b; unpack2(v, a, b); return a + b;
}

// ---------------- activations ----------------
__device__ __forceinline__ float sigf(float x) {
    return __fdividef(1.0f, 1.0f + __expf(-x));
}
__device__ __forceinline__ float tanhf_(float x) {
    return __fdividef(2.0f, 1.0f + __expf(-2.0f * x)) - 1.0f;
}

// ---------------- conv1d (causal k=5, 1->64) + relu + fused bf16 split -----
__global__ void conv_kernel(const float* __restrict__ x, const float* __restrict__ w,
                            const float* __restrict__ bias, __nv_bfloat16* __restrict__ ap)
{
    int tid = threadIdx.x;            // 256
    int c   = tid & 63;
    int ts  = tid >> 6;
    int t   = blockIdx.x * 4 + ts;
    int b   = blockIdx.y;
    float acc = bias[c];
#pragma unroll
    for (int k = 0; k < 5; k++) {
        int xi = t - 4 + k;
        float xv = (xi >= 0) ? x[(size_t)b * T_SEQ + xi] : 0.0f;
        acc = fmaf(xv, w[c * 5 + k], acc);
    }
    float v = fmaxf(acc, 0.0f);
    __nv_bfloat16 hi = __float2bfloat16(v);
    __nv_bfloat16 lo = __float2bfloat16(v - __bfloat162float(hi));
    size_t base = ((size_t)t * B_SZ + b) * 192;
    ap[base + c]       = hi;
    ap[base + 64 + c]  = hi;
    ap[base + 128 + c] = lo;
}

// ---------------- split fp32 -> bf16 along K (weights only) ---------------
__global__ void split2_kernel(const float* __restrict__ src, __nv_bfloat16* __restrict__ dst,
                              int total2, int Khalf, int K)
{
    int i = blockIdx.x * blockDim.x + threadIdx.x;
    if (i >= total2) return;
    int r = i / Khalf;
    int k = (i - r * Khalf) * 2;
    float2 v = *(const float2*)(src + (size_t)r * K + k);
    __nv_bfloat16 hx = __float2bfloat16(v.x);
    __nv_bfloat16 hy = __float2bfloat16(v.y);
    __nv_bfloat16 lx = __float2bfloat16(v.x - __bfloat162float(hx));
    __nv_bfloat16 ly = __float2bfloat16(v.y - __bfloat162float(hy));
    __nv_bfloat162 hi; hi.x = hx; hi.y = hy;
    __nv_bfloat162 lo; lo.x = lx; lo.y = ly;
    __nv_bfloat16* d = dst + (size_t)r * 3 * K + k;
    *(__nv_bfloat162*)(d)         = hi;
    *(__nv_bfloat162*)(d + K)     = lo;
    *(__nv_bfloat162*)(d + 2 * K) = hi;
}

// ---------------- HMMA GEMM (unchanged, passing) ---------------------------
#define GSTAGES 4
#define LDT_B   80
#define TILE_B  (128 * LDT_B)
#define STAGE_B (2 * TILE_B)
#define GSMEM   (GSTAGES * STAGE_B)

__global__ __launch_bounds__(256)
void gemm_mma(const __nv_bfloat16* __restrict__ A, const __nv_bfloat16* __restrict__ W,
              const float* __restrict__ bias, float* __restrict__ C,
              int Kp, int ldc)
{
    extern __shared__ char sm[];
    const uint32_t sbase = smem_to_u32(sm);
    const int tid  = threadIdx.x;
    const int wid  = tid >> 5, lane = tid & 31;
    const int wm   = wid & 3;
    const int wn   = wid >> 2;
    const int n0   = blockIdx.x * 128;
    const int m0   = blockIdx.y * 128;
    const int NK   = Kp >> 5;
    const size_t rowBytes = (size_t)Kp * 2;

    const char* Ag = (const char*)(A + (size_t)m0 * Kp);
    const char* Wg = (const char*)(W + (size_t)n0 * Kp);

    const int lrow = tid >> 1;
    const int lc0  = (tid & 1) * 32;

    auto load_stage = [&](int s, int kb) {
        uint32_t ab = sbase + s * STAGE_B;
        uint32_t bb = ab + TILE_B;
        const char* ga = Ag + (size_t)lrow * rowBytes + (size_t)kb * 64 + lc0;
        const char* gb = Wg + (size_t)lrow * rowBytes + (size_t)kb * 64 + lc0;
        uint32_t da = ab + lrow * LDT_B + lc0;
        uint32_t db = bb + lrow * LDT_B + lc0;
        cp_async16(da,      ga);
        cp_async16(da + 16, ga + 16);
        cp_async16(db,      gb);
        cp_async16(db + 16, gb + 16);
    };

    float acc[2][8][4];
#pragma unroll
    for (int i = 0; i < 2; i++)
#pragma unroll
        for (int j = 0; j < 8; j++)
#pragma unroll
            for (int q = 0; q < 4; q++) acc[i][j][q] = 0.0f;

#pragma unroll
    for (int s = 0; s < GSTAGES - 1; s++) {
        if (s < NK) load_stage(s, s);
        cp_commit();
    }

    const int lr16 = lane & 15;
    const int chi  = (lane >> 4) * 16;

    for (int i = 0; i < NK; i++) {
        cp_wait<GSTAGES - 2>();
        __syncthreads();

        int nk = i + GSTAGES - 1;
        if (nk < NK) load_stage(nk % GSTAGES, nk);
        cp_commit();

        uint32_t ab = sbase + (i % GSTAGES) * STAGE_B;
        uint32_t bb = ab + TILE_B;

#pragma unroll
        for (int ks = 0; ks < 2; ks++) {
            uint32_t af[2][4], bf[4][4];
#pragma unroll
            for (int i2 = 0; i2 < 2; i2++) {
                uint32_t addr = ab + (wm * 32 + i2 * 16 + lr16) * LDT_B + ks * 32 + chi;
                LDSM_X4(af[i2], addr);
            }
#pragma unroll
            for (int jp = 0; jp < 4; jp++) {
                uint32_t addr = bb + (wn * 64 + jp * 16 + lr16) * LDT_B + ks * 32 + chi;
                LDSM_X4(bf[jp], addr);
            }
#pragma unroll
            for (int i2 = 0; i2 < 2; i2++) {
#pragma unroll
                for (int j = 0; j < 8; j++) {
                    int jp = j >> 1;
                    uint32_t b0 = (j & 1) ? bf[jp][1] : bf[jp][0];
                    uint32_t b1 = (j & 1) ? bf[jp][3] : bf[jp][2];
                    MMA16816(acc[i2][j], af[i2], b0, b1);
                }
            }
        }
        __syncthreads();
    }

    const int group = lane >> 2, t4 = lane & 3;
#pragma unroll
    for (int i2 = 0; i2 < 2; i2++) {
        int r0 = m0 + wm * 32 + i2 * 16 + group;
#pragma unroll
        for (int j = 0; j < 8; j++) {
            int cidx = n0 + wn * 64 + j * 8 + t4 * 2;
            float bv0 = bias[cidx], bv1 = bias[cidx + 1];
            float2 v0, v1;
            v0.x = acc[i2][j][0] + bv0; v0.y = acc[i2][j][1] + bv1;
            v1.x = acc[i2][j][2] + bv0; v1.y = acc[i2][j][3] + bv1;
            *(float2*)&C[(size_t)r0 * ldc + cidx]       = v0;
            *(float2*)&C[(size_t)(r0 + 8) * ldc + cidx] = v1;
        }
    }
}

// ---------------- unit-per-thread LSTM scan (H=128, NB=4) ------------------
// 128 threads; thread j owns unit j: 4 gate rows x 4 batches.
// f32x2 lanes packed along k. All smem W reads are dense 16B LDS.128
// (crossbar bytes-floor); h read as 16B quads covering two k-pairs.
#define UKS2  52   // k-pairs in smem (k 0..103)
#define UKR2  12   // k-pairs in regs (k 104..127)
#define USMEM ((2 * UKS2 * 128 * 4 + 2 * 4 * 128) * 4)   // 217088 B

__global__ __launch_bounds__(128, 1)
void lstm_scan_u128(const float* __restrict__ xw,     // [T*B][1024]
                    const float* __restrict__ w_hh,   // [2][512][128]
                    __nv_bfloat16* __restrict__ ap)   // [T*B][768]
{
    const int j   = threadIdx.x;        // unit 0..127
    const int dir = blockIdx.y;
    const int b0  = blockIdx.x * 4;

    extern __shared__ float smf[];
    float* WtA = smf;                         // [UKS2][128][4]: g0,g1 k-pairs
    float* WtB = smf + UKS2 * 128 * 4;        // [UKS2][128][4]: g2,g3 k-pairs
    float* hp  = WtB + UKS2 * 128 * 4;        // [2][4][128] batch-major h

    const float* Wd = w_hh + (size_t)dir * 512 * 128;

    // cooperative W fill: coalesced LDG (k = j), scatter STS
#pragma unroll 4
    for (int r = 0; r < 512; r++) {
        float v = Wd[(size_t)r * 128 + j];
        int g = r >> 7, u = r & 127;
        int k2 = j >> 1, odd = j & 1;
        if (k2 < UKS2) {
            float* base = (g < 2) ? WtA : WtB;
            base[(k2 * 128 + u) * 4 + (g & 1) * 2 + odd] = v;
        }
    }

    // register-resident W for k in [104,128): (k,k+1) pairs per gate
    uint64_t wreg[4][UKR2];
#pragma unroll
    for (int g = 0; g < 4; g++) {
        const float* row = Wd + (size_t)(g * 128 + j) * 128 + 104;
#pragma unroll
        for (int k2 = 0; k2 < UKR2; k2++) {
            float2 w2 = *(const float2*)(row + 2 * k2);
            wreg[g][k2] = pack2(w2.x, w2.y);
        }
    }

    for (int i = j; i < 512; i += 128) hp[i] = 0.0f;

    float c[4] = {0.f, 0.f, 0.f, 0.f};
    const int tstep = dir ? -1 : 1;
    int t = dir ? (T_SEQ - 1) : 0;
    const ptrdiff_t xstep = (ptrdiff_t)tstep * B_SZ * 1024;
    const float* xr = xw + ((size_t)t * B_SZ + b0) * 1024 + dir * 512 + j;

    float nx[4][4];
#pragma unroll
    for (int g = 0; g < 4; g++)
#pragma unroll
        for (int b = 0; b < 4; b++)
            nx[g][b] = xr[b * 1024 + g * 128];

    __syncthreads();

    for (int s = 0; s < T_SEQ; s++, t += tstep) {
        uint64_t acc[4][4];
#pragma unroll
        for (int g = 0; g < 4; g++)
#pragma unroll
            for (int b = 0; b < 4; b++)
                acc[g][b] = pack2(nx[g][b], 0.0f);

        if (s + 1 < T_SEQ) {
            xr += xstep;
#pragma unroll
            for (int g = 0; g < 4; g++)
#pragma unroll
                for (int b = 0; b < 4; b++)
                    nx[g][b] = xr[b * 1024 + g * 128];
        }

        const float* hc = hp + (s & 1) * 512;       // read buffer

        // process two k-pairs per iteration: dense 16B loads for W and h
#pragma unroll 2
        for (int k2 = 0; k2 < UKS2; k2 += 2) {
            ulonglong2 wA0 = *(const ulonglong2*)(WtA + ((k2    ) * 128 + j) * 4);
            ulonglong2 wB0 = *(const ulonglong2*)(WtB + ((k2    ) * 128 + j) * 4);
            ulonglong2 wA1 = *(const ulonglong2*)(WtA + ((k2 + 1) * 128 + j) * 4);
            ulonglong2 wB1 = *(const ulonglong2*)(WtB + ((k2 + 1) * 128 + j) * 4);
            ulonglong2 h0 = *(const ulonglong2*)(hc + 0 * 128 + 2 * k2);
            ulonglong2 h1 = *(const ulonglong2*)(hc + 1 * 128 + 2 * k2);
            ulonglong2 h2 = *(const ulonglong2*)(hc + 2 * 128 + 2 * k2);
            ulonglong2 h3 = *(const ulonglong2*)(hc + 3 * 128 + 2 * k2);
            // k2: lanes (2k2, 2k2+1) = .x
            fma2(acc[0][0], wA0.x, h0.x); fma2(acc[0][1], wA0.x, h1.x);
            fma2(acc[0][2], wA0.x, h2.x); fma2(acc[0][3], wA0.x, h3.x);
            fma2(acc[1][0], wA0.y, h0.x); fma2(acc[1][1], wA0.y, h1.x);
            fma2(acc[1][2], wA0.y, h2.x); fma2(acc[1][3], wA0.y, h3.x);
            fma2(acc[2][0], wB0.x, h0.x); fma2(acc[2][1], wB0.x, h1.x);
            fma2(acc[2][2], wB0.x, h2.x); fma2(acc[2][3], wB0.x, h3.x);
            fma2(acc[3][0], wB0.y, h0.x); fma2(acc[3][1], wB0.y, h1.x);
            fma2(acc[3][2], wB0.y, h2.x); fma2(acc[3][3], wB0.y, h3.x);
            // k2+1: lanes (2k2+2, 2k2+3) = .y
            fma2(acc[0][0], wA1.x, h0.y); fma2(acc[0][1], wA1.x, h1.y);
            fma2(acc[0][2], wA1.x, h2.y); fma2(acc[0][3], wA1.x, h3.y);
            fma2(acc[1][0], wA1.y, h0.y); fma2(acc[1][1], wA1.y, h1.y);
            fma2(acc[1][2], wA1.y, h2.y); fma2(acc[1][3], wA1.y, h3.y);
            fma2(acc[2][0], wB1.x, h0.y); fma2(acc[2][1], wB1.x, h1.y);
            fma2(acc[2][2], wB1.x, h2.y); fma2(acc[2][3], wB1.x, h3.y);
            fma2(acc[3][0], wB1.y, h0.y); fma2(acc[3][1], wB1.y, h1.y);
            fma2(acc[3][2], wB1.y, h2.y); fma2(acc[3][3], wB1.y, h3.y);
        }
#pragma unroll
        for (int k2 = 0; k2 < UKR2; k2 += 2) {
            const float* hk = hc + 104 + 2 * k2;
            ulonglong2 h0 = *(const ulonglong2*)(hk + 0 * 128);
            ulonglong2 h1 = *(const ulonglong2*)(hk + 1 * 128);
            ulonglong2 h2 = *(const ulonglong2*)(hk + 2 * 128);
            ulonglong2 h3 = *(const ulonglong2*)(hk + 3 * 128);
#pragma unroll
            for (int g = 0; g < 4; g++) {
                fma2(acc[g][0], wreg[g][k2], h0.x);
                fma2(acc[g][1], wreg[g][k2], h1.x);
                fma2(acc[g][2], wreg[g][k2], h2.x);
                fma2(acc[g][3], wreg[g][k2], h3.x);
                fma2(acc[g][0], wreg[g][k2 + 1], h0.y);
                fma2(acc[g][1], wreg[g][k2 + 1], h1.y);
                fma2(acc[g][2], wreg[g][k2 + 1], h2.y);
                fma2(acc[g][3], wreg[g][k2 + 1], h3.y);
            }
        }

        float* hn = hp + ((s + 1) & 1) * 512;       // write buffer
        const int col = dir * 128 + j;
#pragma unroll
        for (int b = 0; b < 4; b++) {
            float xi = hadd2(acc[0][b]);
            float xf = hadd2(acc[1][b]);
            float xg = hadd2(acc[2][b]);
            float xo = hadd2(acc[3][b]);
            float si = sigf(xi), sf = sigf(xf), so = sigf(xo);
            float tg = tanhf_(xg);
            c[b] = fmaf(sf, c[b], si * tg);
            float h = so * tanhf_(c[b]);
            hn[b * 128 + j] = h;
            __nv_bfloat16 hi = __float2bfloat16(h);
            __nv_bfloat16 lo = __float2bfloat16(h - __bfloat162float(hi));
            size_t base = ((size_t)t * B_SZ + b0 + b) * 768;
            ap[base + col]       = hi;
            ap[base + 256 + col] = hi;
            ap[base + 512 + col] = lo;
        }
        __syncthreads();
    }
}

// ---------------- unit-per-thread LSTM scan (H=64, fwd, last-only) --------
// 128 threads: thread = (unit j 0..63, batch half bp 0..1). Full W in smem.
#define U64SMEM ((2 * 32 * 64 * 4 + 2 * 2 * 64) * 4)   // 66560 B

__global__ __launch_bounds__(128, 1)
void lstm_scan_u64(const float* __restrict__ xw,    // [T*B][256] (fwd gates)
                   const float* __restrict__ w_hh,  // [2][256][64] (use dir 0)
                   float* __restrict__ h3out)       // [B][128], cols 0..63
{
    const int j  = threadIdx.x & 63;
    const int bp = threadIdx.x >> 6;
    const int b0 = blockIdx.x * 2;

    extern __shared__ float smf[];
    float* WtA = smf;                    // [32][64][4]: g0,g1 k-pairs
    float* WtB = smf + 32 * 64 * 4;      // [32][64][4]: g2,g3 k-pairs
    float* hp  = WtB + 32 * 64 * 4;      // [2][2][64]

    // cooperative W fill: 256 rows x 64 cols, k = j
    for (int r = bp; r < 256; r += 2) {
        float v = w_hh[(size_t)r * 64 + j];
        int g = r >> 6, u = r & 63;
        int k2 = j >> 1, odd = j & 1;
        float* base = (g < 2) ? WtA : WtB;
        base[(k2 * 64 + u) * 4 + (g & 1) * 2 + odd] = v;
    }
    for (int i = threadIdx.x; i < 256; i += 128) hp[i] = 0.0f;

    float c = 0.0f;
    const float* xr = xw + ((size_t)0 * B_SZ + b0 + bp) * 256 + j;
    float nx[4];
#pragma unroll
    for (int g = 0; g < 4; g++) nx[g] = xr[g * 64];
    __syncthreads();

    for (int s = 0; s < T_SEQ; s++) {
        uint64_t acc[4];
#pragma unroll
        for (int g = 0; g < 4; g++) acc[g] = pack2(nx[g], 0.0f);

        if (s + 1 < T_SEQ) {
            xr += (ptrdiff_t)B_SZ * 256;
#pragma unroll
            for (int g = 0; g < 4; g++) nx[g] = xr[g * 64];
        }

        const float* hc = hp + (s & 1) * 128 + bp * 64;
#pragma unroll 4
        for (int k2 = 0; k2 < 32; k2 += 2) {
            ulonglong2 wA0 = *(const ulonglong2*)(WtA + ((k2    ) * 64 + j) * 4);
            ulonglong2 wB0 = *(const ulonglong2*)(WtB + ((k2    ) * 64 + j) * 4);
            ulonglong2 wA1 = *(const ulonglong2*)(WtA + ((k2 + 1) * 64 + j) * 4);
            ulonglong2 wB1 = *(const ulonglong2*)(WtB + ((k2 + 1) * 64 + j) * 4);
            ulonglong2 hv = *(const ulonglong2*)(hc + 2 * k2);
            fma2(acc[0], wA0.x, hv.x); fma2(acc[1], wA0.y, hv.x);
            fma2(acc[2], wB0.x, hv.x); fma2(acc[3], wB0.y, hv.x);
            fma2(acc[0], wA1.x, hv.y); fma2(acc[1], wA1.y, hv.y);
            fma2(acc[2], wB1.x, hv.y); fma2(acc[3], wB1.y, hv.y);
        }

        float xi = hadd2(acc[0]);
        float xf = hadd2(acc[1]);
        float xg = hadd2(acc[2]);
        float xo = hadd2(acc[3]);
        float si = sigf(xi), sf = sigf(xf), so = sigf(xo);
        float tg = tanhf_(xg);
        c = fmaf(sf, c, si * tg);
        float h = so * tanhf_(c);
        hp[((s + 1) & 1) * 128 + bp * 64 + j] = h;
        if (s == T_SEQ - 1) h3out[(size_t)(b0 + bp) * 128 + j] = h;
        __syncthreads();
    }
}

// ---------------- layer-3 backward: single step from zero state -----------
__global__ void lstm3_bwd_last(const float* __restrict__ xwb, float* __restrict__ h3)
{
    int b = blockIdx.x;
    int j = threadIdx.x;  // 0..63
    const float* gr = xwb + b * 256;
    float xi = gr[j], xg = gr[128 + j], xo = gr[192 + j];
    float c = sigf(xi) * tanhf_(xg);
    float h = sigf(xo) * tanhf_(c);
    h3[b * 128 + 64 + j] = h;
}

// ---------------- small FC ----------------
__global__ void fc_kernel(const float* __restrict__ in, const float* __restrict__ w,
                          const float* __restrict__ bias, float* __restrict__ out,
                          int K, int O, int do_relu)
{
    int b = blockIdx.x;
    extern __shared__ float s_in[];
    for (int k = threadIdx.x; k < K; k += blockDim.x) s_in[k] = in[(size_t)b * K + k];
    __syncthreads();
    for (int o = threadIdx.x; o < O; o += blockDim.x) {
        float acc = bias[o];
        const float* wr = w + (size_t)o * K;
        for (int k = 0; k < K; k++) acc = fmaf(s_in[k], wr[k], acc);
        if (do_relu) acc = fmaxf(acc, 0.0f);
        out[(size_t)b * O + o] = acc;
    }
}

// ---------------- host orchestration --------------------------------------
extern "C" void kernel_launch(void* const* d_in, const int* in_sizes, int n_in,
                              void* d_out, int out_size)
{
    const float* x      = (const float*)d_in[0];
    const float* conv_w = (const float*)d_in[1];
    const float* conv_b = (const float*)d_in[2];
    const float* w_ih1  = (const float*)d_in[3];
    const float* w_hh1  = (const float*)d_in[4];
    const float* b1     = (const float*)d_in[5];
    const float* w_ih2  = (const float*)d_in[6];
    const float* w_hh2  = (const float*)d_in[7];
    const float* b2     = (const float*)d_in[8];
    const float* w_ih3  = (const float*)d_in[9];
    const float* w_hh3  = (const float*)d_in[10];
    const float* b3     = (const float*)d_in[11];
    const float* fc1_w  = (const float*)d_in[12];
    const float* fc1_b  = (const float*)d_in[13];
    const float* fc2_w  = (const float*)d_in[14];
    const float* fc2_b  = (const float*)d_in[15];
    const float* fc3_w  = (const float*)d_in[16];
    const float* fc3_b  = (const float*)d_in[17];
    const float* fc4_w  = (const float*)d_in[18];
    const float* fc4_b  = (const float*)d_in[19];
    float* out = (float*)d_out;

    float *pXW, *pXWB3, *pH3, *pF1, *pF2, *pF3;
    __nv_bfloat16 *pAp, *pWp;
    cudaGetSymbolAddress((void**)&pXW,   g_XW);
    cudaGetSymbolAddress((void**)&pAp,   g_Ap);
    cudaGetSymbolAddress((void**)&pWp,   g_Wp);
    cudaGetSymbolAddress((void**)&pXWB3, g_XWB3);
    cudaGetSymbolAddress((void**)&pH3,   g_H3);
    cudaGetSymbolAddress((void**)&pF1,   g_F1);
    cudaGetSymbolAddress((void**)&pF2,   g_F2);
    cudaGetSymbolAddress((void**)&pF3,   g_F3);

    const int M = T_SEQ * B_SZ;  // 262144

    cudaFuncSetAttribute(lstm_scan_u128,
                         cudaFuncAttributeMaxDynamicSharedMemorySize, USMEM);
    cudaFuncSetAttribute(lstm_scan_u64,
                         cudaFuncAttributeMaxDynamicSharedMemorySize, U64SMEM);
    cudaFuncSetAttribute(gemm_mma,
                         cudaFuncAttributeMaxDynamicSharedMemorySize, GSMEM);

    // 1) conv -> A' [t*B+b][192] (fused bf16 split)
    conv_kernel<<<dim3(T_SEQ / 4, B_SZ), 256>>>(x, conv_w, conv_b, pAp);

    // 2) layer 1: W split (K=64 -> 192) + GEMM + unit-scan (writes A'[768])
    split2_kernel<<<(1024 * 32 + 255) / 256, 256>>>(w_ih1, pWp, 1024 * 32, 32, 64);
    gemm_mma<<<dim3(8, M / 128), 256, GSMEM>>>(pAp, pWp, b1, pXW, 192, 1024);
    lstm_scan_u128<<<dim3(B_SZ / 4, 2), 128, USMEM>>>(pXW, w_hh1, pAp);

    // 3) layer 2: K=256 -> 768
    split2_kernel<<<(1024 * 128 + 255) / 256, 256>>>(w_ih2, pWp, 1024 * 128, 128, 256);
    gemm_mma<<<dim3(8, M / 128), 256, GSMEM>>>(pAp, pWp, b2, pXW, 768, 1024);
    lstm_scan_u128<<<dim3(B_SZ / 4, 2), 128, USMEM>>>(pXW, w_hh2, pAp);

    // 4) layer 3 forward: N=256 (fwd gates only), full scan, keep last h
    split2_kernel<<<(512 * 128 + 255) / 256, 256>>>(w_ih3, pWp, 512 * 128, 128, 256);
    gemm_mma<<<dim3(2, M / 128), 256, GSMEM>>>(pAp, pWp, b3, pXW, 768, 256);
    lstm_scan_u64<<<dim3(B_SZ / 2, 1), 128, U64SMEM>>>(pXW, w_hh3, pH3);

    // 5) layer 3 backward at t=T-1 only: one step from zero state
    gemm_mma<<<dim3(2, 2), 256, GSMEM>>>(
        pAp + (size_t)(T_SEQ - 1) * B_SZ * 768,
        pWp + (size_t)256 * 768, b3 + 256, pXWB3, 768, 256);
    lstm3_bwd_last<<<B_SZ, 64>>>(pXWB3, pH3);

    // 6) FC head
    fc_kernel<<<B_SZ, 128, 128 * 4>>>(pH3, fc1_w, fc1_b, pF1, 128, 512, 1);
    fc_kernel<<<B_SZ, 128, 512 * 4>>>(pF1, fc2_w, fc2_b, pF2, 512, 256, 1);
    fc_kernel<<<B_SZ, 128, 256 * 4>>>(pF2, fc3_w, fc3_b, pF3, 256, 128, 1);
    fc_kernel<<<B_SZ, 64, 128 * 4>>>(pF3, fc4_w, fc4_b, out, 128, 2, 0);

    (void)in_sizes; (void)n_in; (void)out_size;
}

// round 11
// speedup vs baseline: 1.0543x; 1.0543x over previous
#include <cuda_runtime.h>
#include <cuda_bf16.h>
#include <cstdint>

#define T_SEQ 1024
#define B_SZ  256

// ---------------- device scratch (allocation-free statics) ----------------
__device__ float g_XW[262144ull * 1024];            // xw fp32 [t*B+b][<=1024]
__device__ __nv_bfloat16 g_Ap[262144ull * 768];     // split-bf16 A' [row][3K]
__device__ __nv_bfloat16 g_Wp[1024ull * 768];       // split-bf16 W' [row][3K]
__device__ float g_XWB3[256 * 256];
__device__ float g_H3[256 * 128];
__device__ float g_F1[256 * 512];
__device__ float g_F2[256 * 256];
__device__ float g_F3[256 * 128];

// ---------------- portable PTX helpers ----------------
__device__ __forceinline__ uint32_t smem_to_u32(const void* p) {
    uint32_t a;
    asm("{ .reg .u64 t; cvta.to.shared.u64 t, %1; cvt.u32.u64 %0, t; }" : "=r"(a) : "l"(p));
    return a;
}
__device__ __forceinline__ void cp_async16(uint32_t dst, const void* src) {
    asm volatile("cp.async.cg.shared.global [%0], [%1], 16;" :: "r"(dst), "l"(src) : "memory");
}
__device__ __forceinline__ void cp_commit() {
    asm volatile("cp.async.commit_group;" ::: "memory");
}
template<int N>
__device__ __forceinline__ void cp_wait() {
    asm volatile("cp.async.wait_group %0;" :: "n"(N) : "memory");
}
#define LDSM_X4(r, addr) \
    asm volatile("ldmatrix.sync.aligned.m8n8.x4.shared.b16 {%0,%1,%2,%3}, [%4];" \
        : "=r"((r)[0]), "=r"((r)[1]), "=r"((r)[2]), "=r"((r)[3]) : "r"(addr))
#define MMA16816(d, a, b0, b1) \
    asm volatile("mma.sync.aligned.m16n8k16.row.col.f32.bf16.bf16.f32 " \
        "{%0,%1,%2,%3}, {%4,%5,%6,%7}, {%8,%9}, {%0,%1,%2,%3};" \
        : "+f"((d)[0]), "+f"((d)[1]), "+f"((d)[2]), "+f"((d)[3]) \
        : "r"((a)[0]), "r"((a)[1]), "r"((a)[2]), "r"((a)[3]), "r"(b0), "r"(b1))

// packed fp32x2 FMA (Blackwell dual-lane fp32): d = a*b + d, lanewise
__device__ __forceinline__ void fma2(uint64_t& d, uint64_t a, uint64_t b) {
    asm("fma.rn.f32x2 %0, %1, %2, %0;" : "+l"(d) : "l"(a), "l"(b));
}
__device__ __forceinline__ uint64_t pack2(float a, float b) {
    uint64_t r;
    asm("mov.b64 %0, {%1, %2};" : "=l"(r) : "f"(a), "f"(b));
    return r;
}
__device__ __forceinline__ void unpack2(uint64_t v, float& a, float& b) {
    asm("mov.b64 {%0, %1}, %2;" : "=f"(a), "=f"(b) : "l"(v));
}
__device__ __forceinline__ float hadd2(uint64_t v) {
    float a, b; unpack2(v, a, b); return a + b;
}

// ---------------- activations ----------------
__device__ __forceinline__ float sigf(float x) {
    return __fdividef(1.0f, 1.0f + __expf(-x));
}
__device__ __forceinline__ float tanhf_(float x) {
    return __fdividef(2.0f, 1.0f + __expf(-2.0f * x)) - 1.0f;
}

// ---------------- conv1d (causal k=5, 1->64) + relu + fused bf16 split -----
__global__ void conv_kernel(const float* __restrict__ x, const float* __restrict__ w,
                            const float* __restrict__ bias, __nv_bfloat16* __restrict__ ap)
{
    int tid = threadIdx.x;            // 256
    int c   = tid & 63;
    int ts  = tid >> 6;
    int t   = blockIdx.x * 4 + ts;
    int b   = blockIdx.y;
    float acc = bias[c];
#pragma unroll
    for (int k = 0; k < 5; k++) {
        int xi = t - 4 + k;
        float xv = (xi >= 0) ? x[(size_t)b * T_SEQ + xi] : 0.0f;
        acc = fmaf(xv, w[c * 5 + k], acc);
    }
    float v = fmaxf(acc, 0.0f);
    __nv_bfloat16 hi = __float2bfloat16(v);
    __nv_bfloat16 lo = __float2bfloat16(v - __bfloat162float(hi));
    size_t base = ((size_t)t * B_SZ + b) * 192;
    ap[base + c]       = hi;
    ap[base + 64 + c]  = hi;
    ap[base + 128 + c] = lo;
}

// ---------------- split fp32 -> bf16 along K (weights only) ---------------
__global__ void split2_kernel(const float* __restrict__ src, __nv_bfloat16* __restrict__ dst,
                              int total2, int Khalf, int K)
{
    int i = blockIdx.x * blockDim.x + threadIdx.x;
    if (i >= total2) return;
    int r = i / Khalf;
    int k = (i - r * Khalf) * 2;
    float2 v = *(const float2*)(src + (size_t)r * K + k);
    __nv_bfloat16 hx = __float2bfloat16(v.x);
    __nv_bfloat16 hy = __float2bfloat16(v.y);
    __nv_bfloat16 lx = __float2bfloat16(v.x - __bfloat162float(hx));
    __nv_bfloat16 ly = __float2bfloat16(v.y - __bfloat162float(hy));
    __nv_bfloat162 hi; hi.x = hx; hi.y = hy;
    __nv_bfloat162 lo; lo.x = lx; lo.y = ly;
    __nv_bfloat16* d = dst + (size_t)r * 3 * K + k;
    *(__nv_bfloat162*)(d)         = hi;
    *(__nv_bfloat162*)(d + K)     = lo;
    *(__nv_bfloat162*)(d + 2 * K) = hi;
}

// ---------------- HMMA GEMM (unchanged, passing) ---------------------------
#define GSTAGES 4
#define LDT_B   80
#define TILE_B  (128 * LDT_B)
#define STAGE_B (2 * TILE_B)
#define GSMEM   (GSTAGES * STAGE_B)

__global__ __launch_bounds__(256)
void gemm_mma(const __nv_bfloat16* __restrict__ A, const __nv_bfloat16* __restrict__ W,
              const float* __restrict__ bias, float* __restrict__ C,
              int Kp, int ldc)
{
    extern __shared__ char sm[];
    const uint32_t sbase = smem_to_u32(sm);
    const int tid  = threadIdx.x;
    const int wid  = tid >> 5, lane = tid & 31;
    const int wm   = wid & 3;
    const int wn   = wid >> 2;
    const int n0   = blockIdx.x * 128;
    const int m0   = blockIdx.y * 128;
    const int NK   = Kp >> 5;
    const size_t rowBytes = (size_t)Kp * 2;

    const char* Ag = (const char*)(A + (size_t)m0 * Kp);
    const char* Wg = (const char*)(W + (size_t)n0 * Kp);

    const int lrow = tid >> 1;
    const int lc0  = (tid & 1) * 32;

    auto load_stage = [&](int s, int kb) {
        uint32_t ab = sbase + s * STAGE_B;
        uint32_t bb = ab + TILE_B;
        const char* ga = Ag + (size_t)lrow * rowBytes + (size_t)kb * 64 + lc0;
        const char* gb = Wg + (size_t)lrow * rowBytes + (size_t)kb * 64 + lc0;
        uint32_t da = ab + lrow * LDT_B + lc0;
        uint32_t db = bb + lrow * LDT_B + lc0;
        cp_async16(da,      ga);
        cp_async16(da + 16, ga + 16);
        cp_async16(db,      gb);
        cp_async16(db + 16, gb + 16);
    };

    float acc[2][8][4];
#pragma unroll
    for (int i = 0; i < 2; i++)
#pragma unroll
        for (int j = 0; j < 8; j++)
#pragma unroll
            for (int q = 0; q < 4; q++) acc[i][j][q] = 0.0f;

#pragma unroll
    for (int s = 0; s < GSTAGES - 1; s++) {
        if (s < NK) load_stage(s, s);
        cp_commit();
    }

    const int lr16 = lane & 15;
    const int chi  = (lane >> 4) * 16;

    for (int i = 0; i < NK; i++) {
        cp_wait<GSTAGES - 2>();
        __syncthreads();

        int nk = i + GSTAGES - 1;
        if (nk < NK) load_stage(nk % GSTAGES, nk);
        cp_commit();

        uint32_t ab = sbase + (i % GSTAGES) * STAGE_B;
        uint32_t bb = ab + TILE_B;

#pragma unroll
        for (int ks = 0; ks < 2; ks++) {
            uint32_t af[2][4], bf[4][4];
#pragma unroll
            for (int i2 = 0; i2 < 2; i2++) {
                uint32_t addr = ab + (wm * 32 + i2 * 16 + lr16) * LDT_B + ks * 32 + chi;
                LDSM_X4(af[i2], addr);
            }
#pragma unroll
            for (int jp = 0; jp < 4; jp++) {
                uint32_t addr = bb + (wn * 64 + jp * 16 + lr16) * LDT_B + ks * 32 + chi;
                LDSM_X4(bf[jp], addr);
            }
#pragma unroll
            for (int i2 = 0; i2 < 2; i2++) {
#pragma unroll
                for (int j = 0; j < 8; j++) {
                    int jp = j >> 1;
                    uint32_t b0 = (j & 1) ? bf[jp][1] : bf[jp][0];
                    uint32_t b1 = (j & 1) ? bf[jp][3] : bf[jp][2];
                    MMA16816(acc[i2][j], af[i2], b0, b1);
                }
            }
        }
        __syncthreads();
    }

    const int group = lane >> 2, t4 = lane & 3;
#pragma unroll
    for (int i2 = 0; i2 < 2; i2++) {
        int r0 = m0 + wm * 32 + i2 * 16 + group;
#pragma unroll
        for (int j = 0; j < 8; j++) {
            int cidx = n0 + wn * 64 + j * 8 + t4 * 2;
            float bv0 = bias[cidx], bv1 = bias[cidx + 1];
            float2 v0, v1;
            v0.x = acc[i2][j][0] + bv0; v0.y = acc[i2][j][1] + bv1;
            v1.x = acc[i2][j][2] + bv0; v1.y = acc[i2][j][3] + bv1;
            *(float2*)&C[(size_t)r0 * ldc + cidx]       = v0;
            *(float2*)&C[(size_t)(r0 + 8) * ldc + cidx] = v1;
        }
    }
}

// ---------------- LSTM scan H=128: 2-warp k-split + reduction --------------
// 256 threads = (unit j 0..127, k-half kh 0..1). CTA = 4 batches, one dir.
// kh covers 26 smem k-pairs + 6 register k-pairs (512 FMA2/thread/step).
// kh=1 writes hadd2 partials to red[16][128]; kh=0 reduces + updates state.
#define UKS2  52            // smem k-pairs total (26 per half), k 0..103
#define UKRH  6             // register k-pairs per half, k 104..127
#define USMEM ((2 * UKS2 * 128 * 4 + 2 * 4 * 128 + 16 * 128) * 4)  // 225280 B

__global__ __launch_bounds__(256, 1)
void lstm_scan_u128(const float* __restrict__ xw,     // [T*B][1024]
                    const float* __restrict__ w_hh,   // [2][512][128]
                    __nv_bfloat16* __restrict__ ap)   // [T*B][768]
{
    const int tid = threadIdx.x;
    const int j   = tid & 127;
    const int kh  = tid >> 7;
    const int dir = blockIdx.y;
    const int b0  = blockIdx.x * 4;

    extern __shared__ float smf[];
    float* WtA = smf;                         // [UKS2][128][4]: g0,g1 k-pairs
    float* WtB = smf + UKS2 * 128 * 4;        // [UKS2][128][4]: g2,g3 k-pairs
    float* hp  = WtB + UKS2 * 128 * 4;        // [2][4][128]
    float* red = hp + 2 * 4 * 128;            // [16][128]

    const float* Wd = w_hh + (size_t)dir * 512 * 128;

    // cooperative W fill: coalesced LDG, scatter STS (k-pairs 0..51)
#pragma unroll 4
    for (int r = kh; r < 512; r += 2) {
        float v = Wd[(size_t)r * 128 + j];
        int g = r >> 7, u = r & 127;
        int k2 = j >> 1, odd = j & 1;
        if (k2 < UKS2) {
            float* base = (g < 2) ? WtA : WtB;
            base[(k2 * 128 + u) * 4 + (g & 1) * 2 + odd] = v;
        }
    }

    // register W: this half's 6 k-pairs in [104 + kh*12, ...)
    uint64_t wreg[4][UKRH];
#pragma unroll
    for (int g = 0; g < 4; g++) {
        const float* row = Wd + (size_t)(g * 128 + j) * 128 + 104 + kh * 12;
#pragma unroll
        for (int k2 = 0; k2 < UKRH; k2++) {
            float2 w2 = *(const float2*)(row + 2 * k2);
            wreg[g][k2] = pack2(w2.x, w2.y);
        }
    }

    for (int i = tid; i < 1024; i += 256) hp[i] = 0.0f;

    float c[4] = {0.f, 0.f, 0.f, 0.f};
    const int tstep = dir ? -1 : 1;
    int t = dir ? (T_SEQ - 1) : 0;
    const ptrdiff_t xstep = (ptrdiff_t)tstep * B_SZ * 1024;
    const float* xr = xw + ((size_t)t * B_SZ + b0) * 1024 + dir * 512 + j;

    float nx[4][4];
    if (kh == 0) {
#pragma unroll
        for (int g = 0; g < 4; g++)
#pragma unroll
            for (int b = 0; b < 4; b++)
                nx[g][b] = xr[b * 1024 + g * 128];
    }

    __syncthreads();

    const int kbase = kh * 26;
    for (int s = 0; s < T_SEQ; s++, t += tstep) {
        uint64_t acc[4][4];
        if (kh == 0) {
#pragma unroll
            for (int g = 0; g < 4; g++)
#pragma unroll
                for (int b = 0; b < 4; b++)
                    acc[g][b] = pack2(nx[g][b], 0.0f);
            if (s + 1 < T_SEQ) {
                xr += xstep;
#pragma unroll
                for (int g = 0; g < 4; g++)
#pragma unroll
                    for (int b = 0; b < 4; b++)
                        nx[g][b] = xr[b * 1024 + g * 128];
            }
        } else {
#pragma unroll
            for (int g = 0; g < 4; g++)
#pragma unroll
                for (int b = 0; b < 4; b++)
                    acc[g][b] = 0ull;
        }

        const float* hc = hp + (s & 1) * 512;

        // smem part: 13 iterations x 2 k-pairs (dense 16B W and h loads)
#pragma unroll
        for (int k2l = 0; k2l < 26; k2l += 2) {
            const int k2 = kbase + k2l;
            ulonglong2 wA0 = *(const ulonglong2*)(WtA + ((k2    ) * 128 + j) * 4);
            ulonglong2 wB0 = *(const ulonglong2*)(WtB + ((k2    ) * 128 + j) * 4);
            ulonglong2 wA1 = *(const ulonglong2*)(WtA + ((k2 + 1) * 128 + j) * 4);
            ulonglong2 wB1 = *(const ulonglong2*)(WtB + ((k2 + 1) * 128 + j) * 4);
            ulonglong2 h0 = *(const ulonglong2*)(hc + 0 * 128 + 2 * k2);
            ulonglong2 h1 = *(const ulonglong2*)(hc + 1 * 128 + 2 * k2);
            ulonglong2 h2 = *(const ulonglong2*)(hc + 2 * 128 + 2 * k2);
            ulonglong2 h3 = *(const ulonglong2*)(hc + 3 * 128 + 2 * k2);
            fma2(acc[0][0], wA0.x, h0.x); fma2(acc[0][1], wA0.x, h1.x);
            fma2(acc[0][2], wA0.x, h2.x); fma2(acc[0][3], wA0.x, h3.x);
            fma2(acc[1][0], wA0.y, h0.x); fma2(acc[1][1], wA0.y, h1.x);
            fma2(acc[1][2], wA0.y, h2.x); fma2(acc[1][3], wA0.y, h3.x);
            fma2(acc[2][0], wB0.x, h0.x); fma2(acc[2][1], wB0.x, h1.x);
            fma2(acc[2][2], wB0.x, h2.x); fma2(acc[2][3], wB0.x, h3.x);
            fma2(acc[3][0], wB0.y, h0.x); fma2(acc[3][1], wB0.y, h1.x);
            fma2(acc[3][2], wB0.y, h2.x); fma2(acc[3][3], wB0.y, h3.x);
            fma2(acc[0][0], wA1.x, h0.y); fma2(acc[0][1], wA1.x, h1.y);
            fma2(acc[0][2], wA1.x, h2.y); fma2(acc[0][3], wA1.x, h3.y);
            fma2(acc[1][0], wA1.y, h0.y); fma2(acc[1][1], wA1.y, h1.y);
            fma2(acc[1][2], wA1.y, h2.y); fma2(acc[1][3], wA1.y, h3.y);
            fma2(acc[2][0], wB1.x, h0.y); fma2(acc[2][1], wB1.x, h1.y);
            fma2(acc[2][2], wB1.x, h2.y); fma2(acc[2][3], wB1.x, h3.y);
            fma2(acc[3][0], wB1.y, h0.y); fma2(acc[3][1], wB1.y, h1.y);
            fma2(acc[3][2], wB1.y, h2.y); fma2(acc[3][3], wB1.y, h3.y);
        }
        // register part: 3 iterations x 2 k-pairs, h at 104 + kh*12
#pragma unroll
        for (int k2l = 0; k2l < UKRH; k2l += 2) {
            const float* hk = hc + 104 + kh * 12 + 2 * k2l;
            ulonglong2 h0 = *(const ulonglong2*)(hk + 0 * 128);
            ulonglong2 h1 = *(const ulonglong2*)(hk + 1 * 128);
            ulonglong2 h2 = *(const ulonglong2*)(hk + 2 * 128);
            ulonglong2 h3 = *(const ulonglong2*)(hk + 3 * 128);
#pragma unroll
            for (int g = 0; g < 4; g++) {
                fma2(acc[g][0], wreg[g][k2l], h0.x);
                fma2(acc[g][1], wreg[g][k2l], h1.x);
                fma2(acc[g][2], wreg[g][k2l], h2.x);
                fma2(acc[g][3], wreg[g][k2l], h3.x);
                fma2(acc[g][0], wreg[g][k2l + 1], h0.y);
                fma2(acc[g][1], wreg[g][k2l + 1], h1.y);
                fma2(acc[g][2], wreg[g][k2l + 1], h2.y);
                fma2(acc[g][3], wreg[g][k2l + 1], h3.y);
            }
        }

        if (kh == 1) {
#pragma unroll
            for (int g = 0; g < 4; g++)
#pragma unroll
                for (int b = 0; b < 4; b++)
                    red[(g * 4 + b) * 128 + j] = hadd2(acc[g][b]);
        }
        __syncthreads();

        if (kh == 0) {
            float* hn = hp + ((s + 1) & 1) * 512;
            const int col = dir * 128 + j;
#pragma unroll
            for (int b = 0; b < 4; b++) {
                float xi = hadd2(acc[0][b]) + red[(0 * 4 + b) * 128 + j];
                float xf = hadd2(acc[1][b]) + red[(1 * 4 + b) * 128 + j];
                float xg = hadd2(acc[2][b]) + red[(2 * 4 + b) * 128 + j];
                float xo = hadd2(acc[3][b]) + red[(3 * 4 + b) * 128 + j];
                float si = sigf(xi), sf = sigf(xf), so = sigf(xo);
                float tg = tanhf_(xg);
                c[b] = fmaf(sf, c[b], si * tg);
                float h = so * tanhf_(c[b]);
                hn[b * 128 + j] = h;
                __nv_bfloat16 hi = __float2bfloat16(h);
                __nv_bfloat16 lo = __float2bfloat16(h - __bfloat162float(hi));
                size_t base = ((size_t)t * B_SZ + b0 + b) * 768;
                ap[base + col]       = hi;
                ap[base + 256 + col] = hi;
                ap[base + 512 + col] = lo;
            }
        }
        __syncthreads();
    }
}

// ---------------- LSTM scan H=64 (fwd, last-only): k-split + reduction -----
// 256 threads = (unit j 0..63, batch b 0..1, k-half kh 0..1). Full W in smem.
#define U64SMEM ((2 * 32 * 64 * 4 + 2 * 2 * 64 + 8 * 64) * 4)   // 68608 B

__global__ __launch_bounds__(256, 1)
void lstm_scan_u64(const float* __restrict__ xw,    // [T*B][256] (fwd gates)
                   const float* __restrict__ w_hh,  // [2][256][64] (use dir 0)
                   float* __restrict__ h3out)       // [B][128], cols 0..63
{
    const int tid = threadIdx.x;
    const int j   = tid & 63;
    const int b   = (tid >> 6) & 1;
    const int kh  = tid >> 7;
    const int b0  = blockIdx.x * 2;

    extern __shared__ float smf[];
    float* WtA = smf;                    // [32][64][4]: g0,g1 k-pairs
    float* WtB = smf + 32 * 64 * 4;      // [32][64][4]: g2,g3 k-pairs
    float* hp  = WtB + 32 * 64 * 4;      // [2][2][64]
    float* red = hp + 2 * 2 * 64;        // [8][64]  (g*2+b)

    // cooperative W fill: 256 rows x 64 cols
    for (int r = tid >> 6; r < 256; r += 4) {
        float v = w_hh[(size_t)r * 64 + j];
        int g = r >> 6, u = r & 63;
        int k2 = j >> 1, odd = j & 1;
        float* base = (g < 2) ? WtA : WtB;
        base[(k2 * 64 + u) * 4 + (g & 1) * 2 + odd] = v;
    }
    for (int i = tid; i < 256; i += 256) hp[i] = 0.0f;

    float c = 0.0f;
    const float* xr = xw + ((size_t)0 * B_SZ + b0 + b) * 256 + j;
    float nx[4];
    if (kh == 0) {
#pragma unroll
        for (int g = 0; g < 4; g++) nx[g] = xr[g * 64];
    }
    __syncthreads();

    const int kbase = kh * 16;
    for (int s = 0; s < T_SEQ; s++) {
        uint64_t acc[4];
        if (kh == 0) {
#pragma unroll
            for (int g = 0; g < 4; g++) acc[g] = pack2(nx[g], 0.0f);
            if (s + 1 < T_SEQ) {
                xr += (ptrdiff_t)B_SZ * 256;
#pragma unroll
                for (int g = 0; g < 4; g++) nx[g] = xr[g * 64];
            }
        } else {
#pragma unroll
            for (int g = 0; g < 4; g++) acc[g] = 0ull;
        }

        const float* hc = hp + (s & 1) * 128 + b * 64;
#pragma unroll
        for (int k2l = 0; k2l < 16; k2l += 2) {
            const int k2 = kbase + k2l;
            ulonglong2 wA0 = *(const ulonglong2*)(WtA + ((k2    ) * 64 + j) * 4);
            ulonglong2 wB0 = *(const ulonglong2*)(WtB + ((k2    ) * 64 + j) * 4);
            ulonglong2 wA1 = *(const ulonglong2*)(WtA + ((k2 + 1) * 64 + j) * 4);
            ulonglong2 wB1 = *(const ulonglong2*)(WtB + ((k2 + 1) * 64 + j) * 4);
            ulonglong2 hv = *(const ulonglong2*)(hc + 2 * k2);
            fma2(acc[0], wA0.x, hv.x); fma2(acc[1], wA0.y, hv.x);
            fma2(acc[2], wB0.x, hv.x); fma2(acc[3], wB0.y, hv.x);
            fma2(acc[0], wA1.x, hv.y); fma2(acc[1], wA1.y, hv.y);
            fma2(acc[2], wB1.x, hv.y); fma2(acc[3], wB1.y, hv.y);
        }

        if (kh == 1) {
#pragma unroll
            for (int g = 0; g < 4; g++)
                red[(g * 2 + b) * 64 + j] = hadd2(acc[g]);
        }
        __syncthreads();

        if (kh == 0) {
            float xi = hadd2(acc[0]) + red[(0 * 2 + b) * 64 + j];
            float xf = hadd2(acc[1]) + red[(1 * 2 + b) * 64 + j];
            float xg = hadd2(acc[2]) + red[(2 * 2 + b) * 64 + j];
            float xo = hadd2(acc[3]) + red[(3 * 2 + b) * 64 + j];
            float si = sigf(xi), sf = sigf(xf), so = sigf(xo);
            float tg = tanhf_(xg);
            c = fmaf(sf, c, si * tg);
            float h = so * tanhf_(c);
            hp[((s + 1) & 1) * 128 + b * 64 + j] = h;
            if (s == T_SEQ - 1) h3out[(size_t)(b0 + b) * 128 + j] = h;
        }
        __syncthreads();
    }
}

// ---------------- layer-3 backward: single step from zero state -----------
__global__ void lstm3_bwd_last(const float* __restrict__ xwb, float* __restrict__ h3)
{
    int b = blockIdx.x;
    int j = threadIdx.x;  // 0..63
    const float* gr = xwb + b * 256;
    float xi = gr[j], xg = gr[128 + j], xo = gr[192 + j];
    float c = sigf(xi) * tanhf_(xg);
    float h = sigf(xo) * tanhf_(c);
    h3[b * 128 + 64 + j] = h;
}

// ---------------- small FC ----------------
__global__ void fc_kernel(const float* __restrict__ in, const float* __restrict__ w,
                          const float* __restrict__ bias, float* __restrict__ out,
                          int K, int O, int do_relu)
{
    int b = blockIdx.x;
    extern __shared__ float s_in[];
    for (int k = threadIdx.x; k < K; k += blockDim.x) s_in[k] = in[(size_t)b * K + k];
    __syncthreads();
    for (int o = threadIdx.x; o < O; o += blockDim.x) {
        float acc = bias[o];
        const float* wr = w + (size_t)o * K;
        for (int k = 0; k < K; k++) acc = fmaf(s_in[k], wr[k], acc);
        if (do_relu) acc = fmaxf(acc, 0.0f);
        out[(size_t)b * O + o] = acc;
    }
}

// ---------------- host orchestration --------------------------------------
extern "C" void kernel_launch(void* const* d_in, const int* in_sizes, int n_in,
                              void* d_out, int out_size)
{
    const float* x      = (const float*)d_in[0];
    const float* conv_w = (const float*)d_in[1];
    const float* conv_b = (const float*)d_in[2];
    const float* w_ih1  = (const float*)d_in[3];
    const float* w_hh1  = (const float*)d_in[4];
    const float* b1     = (const float*)d_in[5];
    const float* w_ih2  = (const float*)d_in[6];
    const float* w_hh2  = (const float*)d_in[7];
    const float* b2     = (const float*)d_in[8];
    const float* w_ih3  = (const float*)d_in[9];
    const float* w_hh3  = (const float*)d_in[10];
    const float* b3     = (const float*)d_in[11];
    const float* fc1_w  = (const float*)d_in[12];
    const float* fc1_b  = (const float*)d_in[13];
    const float* fc2_w  = (const float*)d_in[14];
    const float* fc2_b  = (const float*)d_in[15];
    const float* fc3_w  = (const float*)d_in[16];
    const float* fc3_b  = (const float*)d_in[17];
    const float* fc4_w  = (const float*)d_in[18];
    const float* fc4_b  = (const float*)d_in[19];
    float* out = (float*)d_out;

    float *pXW, *pXWB3, *pH3, *pF1, *pF2, *pF3;
    __nv_bfloat16 *pAp, *pWp;
    cudaGetSymbolAddress((void**)&pXW,   g_XW);
    cudaGetSymbolAddress((void**)&pAp,   g_Ap);
    cudaGetSymbolAddress((void**)&pWp,   g_Wp);
    cudaGetSymbolAddress((void**)&pXWB3, g_XWB3);
    cudaGetSymbolAddress((void**)&pH3,   g_H3);
    cudaGetSymbolAddress((void**)&pF1,   g_F1);
    cudaGetSymbolAddress((void**)&pF2,   g_F2);
    cudaGetSymbolAddress((void**)&pF3,   g_F3);

    const int M = T_SEQ * B_SZ;  // 262144

    cudaFuncSetAttribute(lstm_scan_u128,
                         cudaFuncAttributeMaxDynamicSharedMemorySize, USMEM);
    cudaFuncSetAttribute(lstm_scan_u64,
                         cudaFuncAttributeMaxDynamicSharedMemorySize, U64SMEM);
    cudaFuncSetAttribute(gemm_mma,
                         cudaFuncAttributeMaxDynamicSharedMemorySize, GSMEM);

    // 1) conv -> A' [t*B+b][192] (fused bf16 split)
    conv_kernel<<<dim3(T_SEQ / 4, B_SZ), 256>>>(x, conv_w, conv_b, pAp);

    // 2) layer 1: W split (K=64 -> 192) + GEMM + unit-scan (writes A'[768])
    split2_kernel<<<(1024 * 32 + 255) / 256, 256>>>(w_ih1, pWp, 1024 * 32, 32, 64);
    gemm_mma<<<dim3(8, M / 128), 256, GSMEM>>>(pAp, pWp, b1, pXW, 192, 1024);
    lstm_scan_u128<<<dim3(B_SZ / 4, 2), 256, USMEM>>>(pXW, w_hh1, pAp);

    // 3) layer 2: K=256 -> 768
    split2_kernel<<<(1024 * 128 + 255) / 256, 256>>>(w_ih2, pWp, 1024 * 128, 128, 256);
    gemm_mma<<<dim3(8, M / 128), 256, GSMEM>>>(pAp, pWp, b2, pXW, 768, 1024);
    lstm_scan_u128<<<dim3(B_SZ / 4, 2), 256, USMEM>>>(pXW, w_hh2, pAp);

    // 4) layer 3 forward: N=256 (fwd gates only), full scan, keep last h
    split2_kernel<<<(512 * 128 + 255) / 256, 256>>>(w_ih3, pWp, 512 * 128, 128, 256);
    gemm_mma<<<dim3(2, M / 128), 256, GSMEM>>>(pAp, pWp, b3, pXW, 768, 256);
    lstm_scan_u64<<<dim3(B_SZ / 2, 1), 256, U64SMEM>>>(pXW, w_hh3, pH3);

    // 5) layer 3 backward at t=T-1 only: one step from zero state
    gemm_mma<<<dim3(2, 2), 256, GSMEM>>>(
        pAp + (size_t)(T_SEQ - 1) * B_SZ * 768,
        pWp + (size_t)256 * 768, b3 + 256, pXWB3, 768, 256);
    lstm3_bwd_last<<<B_SZ, 64>>>(pXWB3, pH3);

    // 6) FC head
    fc_kernel<<<B_SZ, 128, 128 * 4>>>(pH3, fc1_w, fc1_b, pF1, 128, 512, 1);
    fc_kernel<<<B_SZ, 128, 512 * 4>>>(pF1, fc2_w, fc2_b, pF2, 512, 256, 1);
    fc_kernel<<<B_SZ, 128, 256 * 4>>>(pF2, fc3_w, fc3_b, pF3, 256, 128, 1);
    fc_kernel<<<B_SZ, 64, 128 * 4>>>(pF3, fc4_w, fc4_b, out, 128, 2, 0);

    (void)in_sizes; (void)n_in; (void)out_size;
}